// round 6
// baseline (speedup 1.0000x reference)
#include <cuda_runtime.h>
#include <math_constants.h>

// Until operator: out[b,t] = tau * lse_k( min(s2[t+k], -tau*lse_{j<=k}(-s1[t+j]/tau)) / tau )
// over k = 0..127, tau = 0.01. Base-2 log domain, inputs pre-scaled by
// C = (1/tau)*log2(e).
//
// - A-side (smooth prefix-min of s1): online LSE with centered Schraudolph
//   bit-trick exp2 (fex2) + select; underflow clamp free via F2I.U32 saturation.
//   q via matched bit-trick log2 -> roundtrip bias cancellation keeps the
//   measured error at ~3e-4 (tolerance 1e-3).
// - M-side: predicate-free online LSE using the unconditional rescale identity
//     mm' = max(mm,cand); ms = ms*ex2(mm-mm') + ex2(cand-mm')
//   Both ex2 are exact MUFU (one arg is always 0 -> exactly 1), so M stays exact.
//   6 issue slots vs 8 for the select form.
// - Exit: tail error = tau * 121 * 2^(q-mm) / ms < 1.5e-4, i.e.
//   q < mm + log2(ms) - 13 (bit-trick log2), checked per 8-step chunk.

#define TILE   128
#define WSTEPS 128
#define CHUNK  8

__device__ __forceinline__ float ex2f(float x) {
    float r; asm("ex2.approx.f32 %0, %1;" : "=f"(r) : "f"(x)); return r;
}
__device__ __forceinline__ float lg2f(float x) {
    float r; asm("lg2.approx.f32 %0, %1;" : "=f"(r) : "f"(x)); return r;
}

// approx 2^z for z <= 0, centered rel err ~±3%. FFMA + F2I.U32 (saturating
// negative -> 0 gives the underflow clamp for free).
__device__ __forceinline__ float fex2(float z) {
    return __uint_as_float(__float2uint_rn(fmaf(z, 8388608.0f, 1064988634.0f)));
}

__global__ __launch_bounds__(TILE)
void until_kernel(const float* __restrict__ g1,
                  const float* __restrict__ g2,
                  float* __restrict__ out, int T) {
    __shared__ float2 sh[TILE + WSTEPS];   // {x = -C*s1, y = C*s2}

    const float C = 144.26950408889634f;  // (1/tau) * log2(e), tau = 0.01

    const int row = blockIdx.y;
    const int t0  = blockIdx.x * TILE;
    const float* r1 = g1 + (size_t)row * T;
    const float* r2 = g2 + (size_t)row * T;

    #pragma unroll
    for (int i = threadIdx.x; i < TILE + WSTEPS; i += TILE) {
        int g = t0 + i;
        float2 v;
        if (g < T) {
            v.x = -C * __ldg(r1 + g);
            v.y =  C * __ldg(r2 + g);
        } else {
            v.x = -1e30f;   // no contribution to A (exp -> 0)
            v.y = -1e30f;   // cand -> -1e30, no contribution to M
        }
        sh[i] = v;
    }
    __syncthreads();

    const float2* __restrict__ p = sh + threadIdx.x;

    // Online logsumexp state (base-2): A (smooth-min of s1), M (smooth-max of cands).
    float am = -1e38f, as = 0.0f;
    float mm = -1e38f, ms = 0.0f;
    float qv = CUDART_INF_F;

    #pragma unroll 1
    for (int kb = 0; kb < WSTEPS; kb += CHUNK) {
        #pragma unroll
        for (int u = 0; u < CHUNK; ++u) {
            float2 v = p[u];
            float x = v.x;                   // -C * s1[t+k]
            float y = v.y;                   //  C * s2[t+k]

            // A <- logaddexp2(A, x)  (select form; centered fex2)
            float d = x - am;
            float e = fex2(fminf(d, -d));    // 2^{-|d|}, free underflow clamp
            as = (d > 0.0f) ? fmaf(as, e, 1.0f) : (as + e);
            am = fmaxf(am, x);

            // q = C*smooth_min so far (bit-trick log2); cand = min(C*s2, q)
            qv = -fmaf((float)__float_as_int(as), 1.1920929e-7f, -126.9565392f) - am;
            float cand = fminf(y, qv);

            // M <- logaddexp2(M, cand): predicate-free, exact MUFU x2
            float mm2 = fmaxf(mm, cand);
            float ea  = ex2f(mm - mm2);      // exactly 1 when mm is the max
            float eb  = ex2f(cand - mm2);    // exactly 1 when cand is the max
            ms = fmaf(ms, ea, eb);
            mm = mm2;
        }
        p += CHUNK;
        // Exit when tail bound tau*121*2^(qv-mm)/ms < 1.5e-4:
        //   qv < mm + (log2(ms) - 13);  log2(ms) via bit trick, -13 folded in.
        float lt = fmaf((float)__float_as_int(ms), 1.1920929e-7f, -139.9565392f);
        if (__all_sync(0xffffffffu, qv < mm + lt)) break;
    }

    // out = tau * M_natural = (mm + log2(ms)) * tau * ln(2)
    out[(size_t)row * T + t0 + threadIdx.x] = (mm + lg2f(ms)) * 0.006931471805599453f;
}

extern "C" void kernel_launch(void* const* d_in, const int* in_sizes, int n_in,
                              void* d_out, int out_size) {
    const float* s1 = (const float*)d_in[0];
    const float* s2 = (const float*)d_in[1];
    float* out = (float*)d_out;

    const int T = 16384;
    const int B = out_size / T;   // 512

    dim3 grid(T / TILE, B);       // (128, 512)
    until_kernel<<<grid, TILE>>>(s1, s2, out, T);
}

// round 7
// speedup vs baseline: 1.1761x; 1.1761x over previous
#include <cuda_runtime.h>
#include <math_constants.h>

// Until operator: out[b,t] = tau * lse_k( min(s2[t+k], -tau*lse_{j<=k}(-s1[t+j]/tau)) / tau )
// over k = 0..127, tau = 0.01. Base-2 log domain, inputs pre-scaled by
// C = (1/tau)*log2(e).
//
// - A-side (smooth prefix-min of s1): sequential online LSE, select form, with
//   centered Schraudolph bit-trick exp2 (underflow clamp free via F2I.U32
//   saturation) and matched bit-trick log2 for q. Measured error 3.06e-4.
// - M-side: QUAD-batched unconditional rescale. Buffer 4 candidates, then
//     mm4 = max(mm, c0..c3); ms = ms*ex2(mm-mm4) + sum ex2(ci-mm4)
//   All ex2 exact MUFU; the max term's arg is exactly 0 -> factor exactly 1.
//   4.5 slots/step, 1.25 MUFU/step (select form: 9 slots, 1 MUFU; R6's
//   per-step rescale: 6 slots, 2.1 MUFU -> MUFU-bound, regressed).
// - Exit: tail error = tau * 121 * 2^(q-mm) / ms < 1.5e-4, i.e.
//   q < mm + log2(ms) - 13 (bit-trick log2), checked per 8-step chunk.

#define TILE   128
#define WSTEPS 128
#define CHUNK  8

__device__ __forceinline__ float ex2f(float x) {
    float r; asm("ex2.approx.f32 %0, %1;" : "=f"(r) : "f"(x)); return r;
}
__device__ __forceinline__ float lg2f(float x) {
    float r; asm("lg2.approx.f32 %0, %1;" : "=f"(r) : "f"(x)); return r;
}

// approx 2^z for z <= 0, centered rel err ~±3%. FFMA + F2I.U32 (saturating
// negative -> 0 gives the underflow clamp for free).
__device__ __forceinline__ float fex2(float z) {
    return __uint_as_float(__float2uint_rn(fmaf(z, 8388608.0f, 1064988634.0f)));
}

__global__ __launch_bounds__(TILE)
void until_kernel(const float* __restrict__ g1,
                  const float* __restrict__ g2,
                  float* __restrict__ out, int T) {
    __shared__ float2 sh[TILE + WSTEPS];   // {x = -C*s1, y = C*s2}

    const float C = 144.26950408889634f;  // (1/tau) * log2(e), tau = 0.01

    const int row = blockIdx.y;
    const int t0  = blockIdx.x * TILE;
    const float* r1 = g1 + (size_t)row * T;
    const float* r2 = g2 + (size_t)row * T;

    #pragma unroll
    for (int i = threadIdx.x; i < TILE + WSTEPS; i += TILE) {
        int g = t0 + i;
        float2 v;
        if (g < T) {
            v.x = -C * __ldg(r1 + g);
            v.y =  C * __ldg(r2 + g);
        } else {
            v.x = -1e30f;   // no contribution to A (exp -> 0)
            v.y = -1e30f;   // cand -> -1e30, no contribution to M
        }
        sh[i] = v;
    }
    __syncthreads();

    const float2* __restrict__ p = sh + threadIdx.x;

    // Online logsumexp state (base-2): A (smooth-min of s1), M (smooth-max of cands).
    float am = -1e38f, as = 0.0f;
    float mm = -1e38f, ms = 0.0f;
    float qv = CUDART_INF_F;

    #pragma unroll 1
    for (int kb = 0; kb < WSTEPS; kb += CHUNK) {
        #pragma unroll
        for (int uq = 0; uq < CHUNK; uq += 4) {
            float c[4];
            // 4 sequential A-steps producing 4 candidates
            #pragma unroll
            for (int u = 0; u < 4; ++u) {
                float2 v = p[uq + u];
                float x = v.x;                 // -C * s1[t+k]
                float d = x - am;
                float e = fex2(fminf(d, -d));  // 2^{-|d|}, free underflow clamp
                as = (d > 0.0f) ? fmaf(as, e, 1.0f) : (as + e);
                am = fmaxf(am, x);
                // q = C*smooth_min so far (bit-trick log2)
                qv = -fmaf((float)__float_as_int(as), 1.1920929e-7f, -126.9565392f) - am;
                c[u] = fminf(v.y, qv);         // cand = min(C*s2, q)
            }
            // Quad M-update: one anchor rescale for 4 candidates, exact MUFU.
            float mm4 = fmaxf(fmaxf(fmaxf(c[0], c[1]), fmaxf(c[2], c[3])), mm);
            float er  = ex2f(mm   - mm4);      // exactly 1 when mm is the max
            float e0  = ex2f(c[0] - mm4);
            float e1  = ex2f(c[1] - mm4);
            float e2  = ex2f(c[2] - mm4);
            float e3  = ex2f(c[3] - mm4);
            ms = (fmaf(ms, er, e0) + e1) + (e2 + e3);
            mm = mm4;
        }
        p += CHUNK;
        // Exit when tail bound tau*121*2^(qv-mm)/ms < 1.5e-4:
        //   qv < mm + (log2(ms) - 13);  log2(ms) via bit trick, -13 folded in.
        float lt = fmaf((float)__float_as_int(ms), 1.1920929e-7f, -139.9565392f);
        if (__all_sync(0xffffffffu, qv < mm + lt)) break;
    }

    // out = tau * M_natural = (mm + log2(ms)) * tau * ln(2)
    out[(size_t)row * T + t0 + threadIdx.x] = (mm + lg2f(ms)) * 0.006931471805599453f;
}

extern "C" void kernel_launch(void* const* d_in, const int* in_sizes, int n_in,
                              void* d_out, int out_size) {
    const float* s1 = (const float*)d_in[0];
    const float* s2 = (const float*)d_in[1];
    float* out = (float*)d_out;

    const int T = 16384;
    const int B = out_size / T;   // 512

    dim3 grid(T / TILE, B);       // (128, 512)
    until_kernel<<<grid, TILE>>>(s1, s2, out, T);
}